// round 14
// baseline (speedup 1.0000x reference)
#include <cuda_runtime.h>
#include <math.h>

#define NHN 50000          // head nodes
#define NTN 50000          // tail nodes
#define NE  1600000        // edges
#define INF 256            // in features
#define OUTF 32
#define NHEAD 4
#define EDGEF 64
#define NET 5
#define FOUT 128           // NHEAD*OUTF
#define NSLOPE 0.2f

#define GEMM_TILES  ((NTN + 127) / 128)            // 391
#define GEMM_PBLOCKS 196                           // persistent GEMM blocks (2 tiles each)
#define EDGEA_BLOCKS ((NE + 255) / 256)            // 6250
#define NODE_BLOCKS (NHN / 4)                      // 12500 (4 nodes/block, 2 warps/node)
#define RES_BLOCKS  ((NE + 255) / 256)             // 6250

// packed f32x2 FMA: acc = a2 * b2 + acc  (per-half)
#define FMA2(acc, a2, b2) \
    asm("fma.rn.f32x2 %0, %1, %2, %0;" : "+l"(acc) : "l"(a2), "l"(b2))

// ---------------- static scratch ----------------
__device__ __align__(16) float  g_htail[(size_t)NTN * FOUT];   // 25.6MB
__device__ __align__(16) float  g_hl[NHN * NHEAD];
__device__ __align__(16) float  g_hr[NTN * NHEAD];
__device__ __align__(16) float  g_he[NET * NHEAD];
__device__ __align__(16) float  g_Wl[NHEAD * INF];
__device__ __align__(16) float  g_Wr[NHEAD * INF];
__device__ __align__(16) float  g_den[NHN * NHEAD];
__device__ int    g_cnt[NHN];
__device__ int    g_ptr[NHN + 1];
__device__ int    g_cur[NHN];
__device__ __align__(16) float4 g_sex[NE];                     // 25.6MB sorted ex
__device__ int    g_sti[NE];                                   // 6.4MB  sorted tail idx
__device__ int    g_hi[NE];                                    // int32 head idx
__device__ int    g_ti[NE];                                    // int32 tail idx
__device__ unsigned char g_tt[NE];                             // edge type
__device__ int    g_idx64;

// ---- robust index fetch: works for int32 or int64 input, clamped in-range ----
__device__ __forceinline__ int fetch_idx(const void* buf, int i, int n, int is64) {
    long long v = is64 ? ((const long long*)buf)[i] : (long long)((const int*)buf)[i];
    int r = (int)v;
    if (r < 0) r = 0;
    if (r >= n) r = n - 1;
    return r;
}

// ========== launch 1: detect dtype + zero cnt/den + fold Wl/Wr + fold he ==========
__global__ void init_kernel(const unsigned* __restrict__ el_raw,
                            const float* __restrict__ W,
                            const float* __restrict__ We,
                            const float* __restrict__ emb,
                            const float* __restrict__ a_l,
                            const float* __restrict__ a_r,
                            const float* __restrict__ a_e) {
    int gtid = blockIdx.x * blockDim.x + threadIdx.x;
    int stride = gridDim.x * blockDim.x;
    if (gtid == 0) {
        int all0 = 1;
        #pragma unroll 8
        for (int i = 0; i < 64; i++)
            if (el_raw[2 * i + 1] != 0u) all0 = 0;
        g_idx64 = all0;
    }
    for (int j = gtid; j < NHN; j += stride) g_cnt[j] = 0;
    for (int j = gtid; j < NHN * NHEAD; j += stride) g_den[j] = 0.f;
    for (int idx = gtid; idx < NHEAD * INF; idx += stride) {
        int h = idx >> 8;
        int k = idx & 255;
        float sl = 0.f, sr = 0.f;
        #pragma unroll
        for (int d = 0; d < OUTF; d++) {
            float w = W[k * FOUT + h * OUTF + d];
            sl += w * a_l[h * OUTF + d];
            sr += w * a_r[h * OUTF + d];
        }
        g_Wl[idx] = sl;
        g_Wr[idx] = sr;
    }
    int gw = gtid >> 5, lane = gtid & 31;
    if (gw < NET * NHEAD) {
        int t = gw / NHEAD, h = gw % NHEAD;
        float s = 0.f;
        #pragma unroll
        for (int half = 0; half < 2; half++) {
            int f = lane + half * 32;
            float ef = 0.f;
            #pragma unroll 8
            for (int k = 0; k < EDGEF; k++)
                ef += emb[t * EDGEF + k] * We[k * (NHEAD * EDGEF) + h * EDGEF + f];
            s += a_e[h * EDGEF + f] * ef;
        }
        #pragma unroll
        for (int off = 16; off; off >>= 1)
            s += __shfl_xor_sync(0xffffffffu, s, off);
        if (lane == 0) g_he[t * NHEAD + h] = s;
    }
}

// ========== launch 2: hist + index conversion ==========
__global__ void hist_kernel(const void* __restrict__ el,
                            const void* __restrict__ te) {
    int e = blockIdx.x * blockDim.x + threadIdx.x;
    if (e >= NE) return;
    int is64 = g_idx64;
    int hi = fetch_idx(el, e, NHN, is64);
    int ti = fetch_idx(el, NE + e, NTN, is64);
    int tt = fetch_idx(te, e, NET, is64);
    g_hi[e] = hi;
    g_ti[e] = ti;
    g_tt[e] = (unsigned char)tt;
    atomicAdd(&g_cnt[hi], 1);
}

// ========== launch 3: block 0 = exclusive scan, blocks 1+ = logits ==========
__device__ __forceinline__ void scan_body(int t) {
    __shared__ int s[256];
    const int C = (NHN + 255) / 256;   // 196
    int start = t * C; if (start > NHN) start = NHN;
    int end = start + C; if (end > NHN) end = NHN;
    int sum = 0;
    for (int i = start; i < end; i++) sum += g_cnt[i];
    s[t] = sum;
    __syncthreads();
    for (int off = 1; off < 256; off <<= 1) {
        int v = (t >= off) ? s[t - off] : 0;
        __syncthreads();
        s[t] += v;
        __syncthreads();
    }
    int run = s[t] - sum;
    for (int i = start; i < end; i++) {
        int c = g_cnt[i];
        g_ptr[i] = run;
        g_cur[i] = run;
        run += c;
    }
    if (t == 255) g_ptr[NHN] = run;
}

__device__ __forceinline__ void logits_body(const float* __restrict__ headf,
                                            const float* __restrict__ tailf,
                                            int bid, int tid) {
    const int GH = NHN / 4, GT = NTN / 4;
    int gw   = bid * 8 + (tid >> 5);
    int lane = tid & 31;
    if (gw >= GH + GT) return;
    const float* src; const float* Wp; float* dst; int r0;
    if (gw < GH) { r0 = gw * 4;        src = headf; Wp = g_Wl; dst = g_hl; }
    else         { r0 = (gw - GH) * 4; src = tailf; Wp = g_Wr; dst = g_hr; }

    float4 x0[4], x1[4];
    #pragma unroll
    for (int rr = 0; rr < 4; rr++) {
        const float4* x = reinterpret_cast<const float4*>(src + (size_t)(r0 + rr) * INF);
        x0[rr] = x[lane]; x1[rr] = x[lane + 32];
    }
    float4 w0[NHEAD], w1[NHEAD];
    #pragma unroll
    for (int h = 0; h < NHEAD; h++) {
        const float4* w = reinterpret_cast<const float4*>(Wp + h * INF);
        w0[h] = w[lane]; w1[h] = w[lane + 32];
    }
    #pragma unroll
    for (int rr = 0; rr < 4; rr++) {
        float p[NHEAD];
        #pragma unroll
        for (int h = 0; h < NHEAD; h++)
            p[h] = x0[rr].x*w0[h].x + x0[rr].y*w0[h].y + x0[rr].z*w0[h].z + x0[rr].w*w0[h].w
                 + x1[rr].x*w1[h].x + x1[rr].y*w1[h].y + x1[rr].z*w1[h].z + x1[rr].w*w1[h].w;
        #pragma unroll
        for (int off = 16; off; off >>= 1) {
            #pragma unroll
            for (int h = 0; h < NHEAD; h++)
                p[h] += __shfl_xor_sync(0xffffffffu, p[h], off);
        }
        if (lane == 0)
            *reinterpret_cast<float4*>(&dst[(r0 + rr) * NHEAD]) =
                make_float4(p[0], p[1], p[2], p[3]);
    }
}

__global__ void scanlogits_kernel(const float* __restrict__ headf,
                                  const float* __restrict__ tailf) {
    if (blockIdx.x == 0) scan_body(threadIdx.x);
    else logits_body(headf, tailf, blockIdx.x - 1, threadIdx.x);
}

// ========== launch 4 (PROFILED): persistent GEMM ∥ edgeA ==========
__device__ __forceinline__ void gemm_tile(const float* __restrict__ X,
                                          const float* __restrict__ W,
                                          int tile, int tid,
                                          float As[8][128], float Bs[8][128]) {
    int tx = tid & 15, ty = tid >> 4;
    int rbase = tile * 128;

    unsigned long long accp[8][4];
    #pragma unroll
    for (int i = 0; i < 8; i++)
        #pragma unroll
        for (int j = 0; j < 4; j++) accp[i][j] = 0ull;

    for (int k0 = 0; k0 < INF; k0 += 8) {
        {
            int arow = rbase + (tid >> 1);
            int ar = arow < NTN ? arow : NTN - 1;
            const float4 av = *reinterpret_cast<const float4*>(
                X + (size_t)ar * INF + k0 + (tid & 1) * 4);
            int kp = (tid & 1) * 4;
            int rr = tid >> 1;
            As[kp + 0][rr] = av.x;
            As[kp + 1][rr] = av.y;
            As[kp + 2][rr] = av.z;
            As[kp + 3][rr] = av.w;
        }
        {
            const float4 bv = *reinterpret_cast<const float4*>(
                W + (size_t)(k0 + (tid >> 5)) * FOUT + (tid & 31) * 4);
            *reinterpret_cast<float4*>(&Bs[tid >> 5][(tid & 31) * 4]) = bv;
        }
        __syncthreads();
        #pragma unroll
        for (int kk = 0; kk < 8; kk++) {
            float a[8];
            float4 t0 = *reinterpret_cast<const float4*>(&As[kk][ty * 4]);
            float4 t1 = *reinterpret_cast<const float4*>(&As[kk][64 + ty * 4]);
            a[0]=t0.x; a[1]=t0.y; a[2]=t0.z; a[3]=t0.w;
            a[4]=t1.x; a[5]=t1.y; a[6]=t1.z; a[7]=t1.w;
            ulonglong2 b01 = *reinterpret_cast<const ulonglong2*>(&Bs[kk][tx * 4]);
            ulonglong2 b23 = *reinterpret_cast<const ulonglong2*>(&Bs[kk][64 + tx * 4]);
            unsigned long long bp0 = b01.x, bp1 = b01.y, bp2 = b23.x, bp3 = b23.y;
            #pragma unroll
            for (int i = 0; i < 8; i++) {
                unsigned long long a2;
                unsigned au = __float_as_uint(a[i]);
                asm("mov.b64 %0, {%1, %1};" : "=l"(a2) : "r"(au));
                FMA2(accp[i][0], a2, bp0);
                FMA2(accp[i][1], a2, bp1);
                FMA2(accp[i][2], a2, bp2);
                FMA2(accp[i][3], a2, bp3);
            }
        }
        __syncthreads();
    }
    #pragma unroll
    for (int i = 0; i < 8; i++) {
        int r = rbase + (i < 4 ? ty * 4 + i : 64 + ty * 4 + (i - 4));
        if (r < NTN) {
            unsigned lo0, hi0, lo1, hi1;
            asm("mov.b64 {%0, %1}, %2;" : "=r"(lo0), "=r"(hi0) : "l"(accp[i][0]));
            asm("mov.b64 {%0, %1}, %2;" : "=r"(lo1), "=r"(hi1) : "l"(accp[i][1]));
            *reinterpret_cast<float4*>(&g_htail[(size_t)r * FOUT + tx * 4]) =
                make_float4(__uint_as_float(lo0), __uint_as_float(hi0),
                            __uint_as_float(lo1), __uint_as_float(hi1));
            asm("mov.b64 {%0, %1}, %2;" : "=r"(lo0), "=r"(hi0) : "l"(accp[i][2]));
            asm("mov.b64 {%0, %1}, %2;" : "=r"(lo1), "=r"(hi1) : "l"(accp[i][3]));
            *reinterpret_cast<float4*>(&g_htail[(size_t)r * FOUT + 64 + tx * 4]) =
                make_float4(__uint_as_float(lo0), __uint_as_float(hi0),
                            __uint_as_float(lo1), __uint_as_float(hi1));
        }
    }
}

__device__ __forceinline__ void edgeA_body(int bid, int tid,
                                           float* __restrict__ alpha_out,
                                           int write_alpha) {
    int e = bid * 256 + tid;
    if (e >= NE) return;
    int hi = g_hi[e];
    int ti = g_ti[e];
    int tt = (int)g_tt[e];
    float4 l = *reinterpret_cast<const float4*>(&g_hl[hi * NHEAD]);
    float4 r = *reinterpret_cast<const float4*>(&g_hr[ti * NHEAD]);
    float4 h = *reinterpret_cast<const float4*>(&g_he[tt * NHEAD]);
    float4 a;
    a.x = l.x + r.x + h.x; a.x = a.x >= 0.f ? a.x : NSLOPE * a.x;
    a.y = l.y + r.y + h.y; a.y = a.y >= 0.f ? a.y : NSLOPE * a.y;
    a.z = l.z + r.z + h.z; a.z = a.z >= 0.f ? a.z : NSLOPE * a.z;
    a.w = l.w + r.w + h.w; a.w = a.w >= 0.f ? a.w : NSLOPE * a.w;
    float4 ex;
    ex.x = expf(a.x); ex.y = expf(a.y); ex.z = expf(a.z); ex.w = expf(a.w);

    float* dp = &g_den[hi * NHEAD];
    asm volatile("red.global.add.v4.f32 [%0], {%1,%2,%3,%4};"
                 :: "l"(dp), "f"(ex.x), "f"(ex.y), "f"(ex.z), "f"(ex.w)
                 : "memory");

    if (write_alpha)    // unscaled ex, coalesced in e; rescaled in launch 5
        *reinterpret_cast<float4*>(&alpha_out[(size_t)e * NHEAD]) = ex;

    int pos = atomicAdd(&g_cur[hi], 1);
    g_sex[pos] = ex;
    g_sti[pos] = ti;
}

__global__ void __launch_bounds__(256, 2)
fat_kernel(const float* __restrict__ X, const float* __restrict__ W,
           float* __restrict__ alpha_out, int write_alpha) {
    __shared__ float As[8][128];
    __shared__ float Bs[8][128];
    int bid = blockIdx.x;
    int tid = threadIdx.x;
    if (bid < GEMM_PBLOCKS) {
        for (int tile = bid; tile < GEMM_TILES; tile += GEMM_PBLOCKS)
            gemm_tile(X, W, tile, tid, As, Bs);
    } else {
        edgeA_body(bid - GEMM_PBLOCKS, tid, alpha_out, write_alpha);
    }
}

// ========== launch 5: edgeC (2 warps/node, 4x pipelined) ∥ alpha rescale ==========
__device__ __forceinline__ float pick_h(const float4& v, int h) {
    return (h == 0) ? v.x : (h == 1) ? v.y : (h == 2) ? v.z : v.w;
}

__device__ __forceinline__ void edgeC_body(int bid, int tid,
                                           float* __restrict__ out,
                                           float4 part[4][33]) {
    int wid  = tid >> 5;
    int np   = wid >> 1;              // node index within block (0..3)
    int half = wid & 1;               // which half-warp-pair member
    int lane = tid & 31;
    int node = bid * 4 + np;
    int p0 = g_ptr[node], p1 = g_ptr[node + 1];
    int h = lane >> 3;

    float4 acc = make_float4(0.f, 0.f, 0.f, 0.f);
    // this warp takes records p0+half, p0+half+2, ... (stride 2); 4x batched
    int j = p0 + half;
    for (; j + 6 < p1; j += 8) {
        float4 e0 = g_sex[j], e1 = g_sex[j+2], e2 = g_sex[j+4], e3 = g_sex[j+6];
        int t0 = g_sti[j], t1 = g_sti[j+2], t2 = g_sti[j+4], t3 = g_sti[j+6];
        float4 v0 = *reinterpret_cast<const float4*>(&g_htail[(size_t)t0 * FOUT + lane * 4]);
        float4 v1 = *reinterpret_cast<const float4*>(&g_htail[(size_t)t1 * FOUT + lane * 4]);
        float4 v2 = *reinterpret_cast<const float4*>(&g_htail[(size_t)t2 * FOUT + lane * 4]);
        float4 v3 = *reinterpret_cast<const float4*>(&g_htail[(size_t)t3 * FOUT + lane * 4]);
        float a0 = pick_h(e0, h), a1 = pick_h(e1, h), a2 = pick_h(e2, h), a3 = pick_h(e3, h);
        acc.x += a0 * v0.x; acc.y += a0 * v0.y; acc.z += a0 * v0.z; acc.w += a0 * v0.w;
        acc.x += a1 * v1.x; acc.y += a1 * v1.y; acc.z += a1 * v1.z; acc.w += a1 * v1.w;
        acc.x += a2 * v2.x; acc.y += a2 * v2.y; acc.z += a2 * v2.z; acc.w += a2 * v2.w;
        acc.x += a3 * v3.x; acc.y += a3 * v3.y; acc.z += a3 * v3.z; acc.w += a3 * v3.w;
    }
    for (; j < p1; j += 2) {
        float4 e0 = g_sex[j];
        int t0 = g_sti[j];
        float4 v0 = *reinterpret_cast<const float4*>(&g_htail[(size_t)t0 * FOUT + lane * 4]);
        float a0 = pick_h(e0, h);
        acc.x += a0 * v0.x; acc.y += a0 * v0.y; acc.z += a0 * v0.z; acc.w += a0 * v0.w;
    }

    if (half == 1) part[np][lane] = acc;
    __syncthreads();
    if (half == 0) {
        float4 o = part[np][lane];
        acc.x += o.x; acc.y += o.y; acc.z += o.z; acc.w += o.w;

        float4 den = *reinterpret_cast<const float4*>(&g_den[node * NHEAD]);
        float d = pick_h(den, h);
        float rdh = d > 0.f ? 1.f / d : 0.f;
        acc.x *= rdh; acc.y *= rdh; acc.z *= rdh; acc.w *= rdh;
        acc.x = acc.x > 0.f ? acc.x : expm1f(acc.x);
        acc.y = acc.y > 0.f ? acc.y : expm1f(acc.y);
        acc.z = acc.z > 0.f ? acc.z : expm1f(acc.z);
        acc.w = acc.w > 0.f ? acc.w : expm1f(acc.w);
        *reinterpret_cast<float4*>(&out[(size_t)node * FOUT + lane * 4]) = acc;
    }
}

__device__ __forceinline__ void rescale_body(int bid, int tid,
                                             float* __restrict__ alpha_out) {
    int e = bid * 256 + tid;
    if (e >= NE) return;
    int hi = g_hi[e];
    float4 den = *reinterpret_cast<const float4*>(&g_den[hi * NHEAD]);
    float4 rd;
    rd.x = den.x > 0.f ? 1.f / den.x : 0.f;
    rd.y = den.y > 0.f ? 1.f / den.y : 0.f;
    rd.z = den.z > 0.f ? 1.f / den.z : 0.f;
    rd.w = den.w > 0.f ? 1.f / den.w : 0.f;
    float4 al = *reinterpret_cast<const float4*>(&alpha_out[(size_t)e * NHEAD]);
    al.x *= rd.x; al.y *= rd.y; al.z *= rd.z; al.w *= rd.w;
    *reinterpret_cast<float4*>(&alpha_out[(size_t)e * NHEAD]) = al;
}

__global__ void edgeC_kernel(float* __restrict__ out,
                             float* __restrict__ alpha_out) {
    __shared__ float4 part[4][33];
    int bid = blockIdx.x;
    if (bid < NODE_BLOCKS) edgeC_body(bid, threadIdx.x, out, part);
    else rescale_body(bid - NODE_BLOCKS, threadIdx.x, alpha_out);
}

extern "C" void kernel_launch(void* const* d_in, const int* in_sizes, int n_in,
                              void* d_out, int out_size) {
    const float* headf = (const float*)d_in[0];
    const float* tailf = (const float*)d_in[1];
    const float* W     = (const float*)d_in[2];
    const float* We    = (const float*)d_in[3];
    const float* emb   = (const float*)d_in[4];
    const float* a_l   = (const float*)d_in[5];
    const float* a_r   = (const float*)d_in[6];
    const float* a_e   = (const float*)d_in[7];
    const void*  el    = d_in[8];
    const void*  te    = d_in[9];

    float* out   = (float*)d_out;
    float* alpha = out + (size_t)NHN * FOUT;
    int write_alpha = (out_size >= NHN * FOUT + NE * NHEAD) ? 1 : 0;

    init_kernel<<<256, 256>>>((const unsigned*)el, W, We, emb, a_l, a_r, a_e); // 1
    hist_kernel<<<(NE + 255) / 256, 256>>>(el, te);                            // 2
    scanlogits_kernel<<<1 + 3125, 256>>>(headf, tailf);                        // 3
    fat_kernel<<<GEMM_PBLOCKS + EDGEA_BLOCKS, 256>>>(tailf, W, alpha, write_alpha); // 4 <- profiled
    edgeC_kernel<<<NODE_BLOCKS + (write_alpha ? RES_BLOCKS : 0), 256>>>(out, alpha); // 5
}

// round 15
// speedup vs baseline: 1.0547x; 1.0547x over previous
#include <cuda_runtime.h>
#include <math.h>

#define NHN 50000          // head nodes
#define NTN 50000          // tail nodes
#define NE  1600000        // edges
#define INF 256            // in features
#define OUTF 32
#define NHEAD 4
#define EDGEF 64
#define NET 5
#define FOUT 128           // NHEAD*OUTF
#define NSLOPE 0.2f

#define GEMM_TILES  ((NTN + 127) / 128)            // 391
#define GEMM_PBLOCKS 196                           // persistent GEMM blocks (2 tiles each)
#define EDGEA_BLOCKS ((NE + 255) / 256)            // 6250
#define NODE_BLOCKS (NHN / 8)                      // 6250 (8 warps/block, 1 node/warp)
#define RES_BLOCKS  ((NE + 255) / 256)             // 6250

// packed f32x2 FMA: acc = a2 * b2 + acc  (per-half)
#define FMA2(acc, a2, b2) \
    asm("fma.rn.f32x2 %0, %1, %2, %0;" : "+l"(acc) : "l"(a2), "l"(b2))

// ---------------- static scratch ----------------
__device__ __align__(16) float  g_htail[(size_t)NTN * FOUT];   // 25.6MB
__device__ __align__(16) float  g_hl[NHN * NHEAD];
__device__ __align__(16) float  g_hr[NTN * NHEAD];
__device__ __align__(16) float  g_he[NET * NHEAD];
__device__ __align__(16) float  g_Wl[NHEAD * INF];
__device__ __align__(16) float  g_Wr[NHEAD * INF];
__device__ __align__(16) float  g_den[NHN * NHEAD];
__device__ int    g_cnt[NHN];
__device__ int    g_ptr[NHN + 1];
__device__ int    g_cur[NHN];
__device__ __align__(16) float4 g_sex[NE];                     // 25.6MB sorted ex
__device__ int    g_sti[NE];                                   // 6.4MB  sorted tail idx
__device__ int    g_hi[NE];                                    // int32 head idx
__device__ int    g_ti[NE];                                    // int32 tail idx
__device__ unsigned char g_tt[NE];                             // edge type
__device__ int    g_idx64;

// ---- robust index fetch: works for int32 or int64 input, clamped in-range ----
__device__ __forceinline__ int fetch_idx(const void* buf, int i, int n, int is64) {
    long long v = is64 ? ((const long long*)buf)[i] : (long long)((const int*)buf)[i];
    int r = (int)v;
    if (r < 0) r = 0;
    if (r >= n) r = n - 1;
    return r;
}

// ========== launch 1: detect dtype + zero cnt/den + fold Wl/Wr + fold he ==========
__global__ void init_kernel(const unsigned* __restrict__ el_raw,
                            const float* __restrict__ W,
                            const float* __restrict__ We,
                            const float* __restrict__ emb,
                            const float* __restrict__ a_l,
                            const float* __restrict__ a_r,
                            const float* __restrict__ a_e) {
    int gtid = blockIdx.x * blockDim.x + threadIdx.x;
    int stride = gridDim.x * blockDim.x;
    if (gtid == 0) {
        int all0 = 1;
        #pragma unroll 8
        for (int i = 0; i < 64; i++)
            if (el_raw[2 * i + 1] != 0u) all0 = 0;
        g_idx64 = all0;
    }
    for (int j = gtid; j < NHN; j += stride) g_cnt[j] = 0;
    for (int j = gtid; j < NHN * NHEAD; j += stride) g_den[j] = 0.f;
    for (int idx = gtid; idx < NHEAD * INF; idx += stride) {
        int h = idx >> 8;
        int k = idx & 255;
        float sl = 0.f, sr = 0.f;
        #pragma unroll
        for (int d = 0; d < OUTF; d++) {
            float w = W[k * FOUT + h * OUTF + d];
            sl += w * a_l[h * OUTF + d];
            sr += w * a_r[h * OUTF + d];
        }
        g_Wl[idx] = sl;
        g_Wr[idx] = sr;
    }
    int gw = gtid >> 5, lane = gtid & 31;
    if (gw < NET * NHEAD) {
        int t = gw / NHEAD, h = gw % NHEAD;
        float s = 0.f;
        #pragma unroll
        for (int half = 0; half < 2; half++) {
            int f = lane + half * 32;
            float ef = 0.f;
            #pragma unroll 8
            for (int k = 0; k < EDGEF; k++)
                ef += emb[t * EDGEF + k] * We[k * (NHEAD * EDGEF) + h * EDGEF + f];
            s += a_e[h * EDGEF + f] * ef;
        }
        #pragma unroll
        for (int off = 16; off; off >>= 1)
            s += __shfl_xor_sync(0xffffffffu, s, off);
        if (lane == 0) g_he[t * NHEAD + h] = s;
    }
}

// ========== launch 2: hist + index conversion ==========
__global__ void hist_kernel(const void* __restrict__ el,
                            const void* __restrict__ te) {
    int e = blockIdx.x * blockDim.x + threadIdx.x;
    if (e >= NE) return;
    int is64 = g_idx64;
    int hi = fetch_idx(el, e, NHN, is64);
    int ti = fetch_idx(el, NE + e, NTN, is64);
    int tt = fetch_idx(te, e, NET, is64);
    g_hi[e] = hi;
    g_ti[e] = ti;
    g_tt[e] = (unsigned char)tt;
    atomicAdd(&g_cnt[hi], 1);
}

// ========== launch 3: block 0 = exclusive scan, blocks 1+ = logits ==========
__device__ __forceinline__ void scan_body(int t) {
    __shared__ int s[256];
    const int C = (NHN + 255) / 256;   // 196
    int start = t * C; if (start > NHN) start = NHN;
    int end = start + C; if (end > NHN) end = NHN;
    int sum = 0;
    for (int i = start; i < end; i++) sum += g_cnt[i];
    s[t] = sum;
    __syncthreads();
    for (int off = 1; off < 256; off <<= 1) {
        int v = (t >= off) ? s[t - off] : 0;
        __syncthreads();
        s[t] += v;
        __syncthreads();
    }
    int run = s[t] - sum;
    for (int i = start; i < end; i++) {
        int c = g_cnt[i];
        g_ptr[i] = run;
        g_cur[i] = run;
        run += c;
    }
    if (t == 255) g_ptr[NHN] = run;
}

__device__ __forceinline__ void logits_body(const float* __restrict__ headf,
                                            const float* __restrict__ tailf,
                                            int bid, int tid) {
    const int GH = NHN / 4, GT = NTN / 4;
    int gw   = bid * 8 + (tid >> 5);
    int lane = tid & 31;
    if (gw >= GH + GT) return;
    const float* src; const float* Wp; float* dst; int r0;
    if (gw < GH) { r0 = gw * 4;        src = headf; Wp = g_Wl; dst = g_hl; }
    else         { r0 = (gw - GH) * 4; src = tailf; Wp = g_Wr; dst = g_hr; }

    float4 x0[4], x1[4];
    #pragma unroll
    for (int rr = 0; rr < 4; rr++) {
        const float4* x = reinterpret_cast<const float4*>(src + (size_t)(r0 + rr) * INF);
        x0[rr] = x[lane]; x1[rr] = x[lane + 32];
    }
    float4 w0[NHEAD], w1[NHEAD];
    #pragma unroll
    for (int h = 0; h < NHEAD; h++) {
        const float4* w = reinterpret_cast<const float4*>(Wp + h * INF);
        w0[h] = w[lane]; w1[h] = w[lane + 32];
    }
    #pragma unroll
    for (int rr = 0; rr < 4; rr++) {
        float p[NHEAD];
        #pragma unroll
        for (int h = 0; h < NHEAD; h++)
            p[h] = x0[rr].x*w0[h].x + x0[rr].y*w0[h].y + x0[rr].z*w0[h].z + x0[rr].w*w0[h].w
                 + x1[rr].x*w1[h].x + x1[rr].y*w1[h].y + x1[rr].z*w1[h].z + x1[rr].w*w1[h].w;
        #pragma unroll
        for (int off = 16; off; off >>= 1) {
            #pragma unroll
            for (int h = 0; h < NHEAD; h++)
                p[h] += __shfl_xor_sync(0xffffffffu, p[h], off);
        }
        if (lane == 0)
            *reinterpret_cast<float4*>(&dst[(r0 + rr) * NHEAD]) =
                make_float4(p[0], p[1], p[2], p[3]);
    }
}

__global__ void scanlogits_kernel(const float* __restrict__ headf,
                                  const float* __restrict__ tailf) {
    if (blockIdx.x == 0) scan_body(threadIdx.x);
    else logits_body(headf, tailf, blockIdx.x - 1, threadIdx.x);
}

// ========== launch 4 (PROFILED): persistent GEMM ∥ edgeA ==========
__device__ __forceinline__ void gemm_tile(const float* __restrict__ X,
                                          const float* __restrict__ W,
                                          int tile, int tid,
                                          float As[8][128], float Bs[8][128]) {
    int tx = tid & 15, ty = tid >> 4;
    int rbase = tile * 128;

    unsigned long long accp[8][4];
    #pragma unroll
    for (int i = 0; i < 8; i++)
        #pragma unroll
        for (int j = 0; j < 4; j++) accp[i][j] = 0ull;

    for (int k0 = 0; k0 < INF; k0 += 8) {
        {
            int arow = rbase + (tid >> 1);
            int ar = arow < NTN ? arow : NTN - 1;
            const float4 av = *reinterpret_cast<const float4*>(
                X + (size_t)ar * INF + k0 + (tid & 1) * 4);
            int kp = (tid & 1) * 4;
            int rr = tid >> 1;
            As[kp + 0][rr] = av.x;
            As[kp + 1][rr] = av.y;
            As[kp + 2][rr] = av.z;
            As[kp + 3][rr] = av.w;
        }
        {
            const float4 bv = *reinterpret_cast<const float4*>(
                W + (size_t)(k0 + (tid >> 5)) * FOUT + (tid & 31) * 4);
            *reinterpret_cast<float4*>(&Bs[tid >> 5][(tid & 31) * 4]) = bv;
        }
        __syncthreads();
        #pragma unroll
        for (int kk = 0; kk < 8; kk++) {
            float a[8];
            float4 t0 = *reinterpret_cast<const float4*>(&As[kk][ty * 4]);
            float4 t1 = *reinterpret_cast<const float4*>(&As[kk][64 + ty * 4]);
            a[0]=t0.x; a[1]=t0.y; a[2]=t0.z; a[3]=t0.w;
            a[4]=t1.x; a[5]=t1.y; a[6]=t1.z; a[7]=t1.w;
            ulonglong2 b01 = *reinterpret_cast<const ulonglong2*>(&Bs[kk][tx * 4]);
            ulonglong2 b23 = *reinterpret_cast<const ulonglong2*>(&Bs[kk][64 + tx * 4]);
            unsigned long long bp0 = b01.x, bp1 = b01.y, bp2 = b23.x, bp3 = b23.y;
            #pragma unroll
            for (int i = 0; i < 8; i++) {
                unsigned long long a2;
                unsigned au = __float_as_uint(a[i]);
                asm("mov.b64 %0, {%1, %1};" : "=l"(a2) : "r"(au));
                FMA2(accp[i][0], a2, bp0);
                FMA2(accp[i][1], a2, bp1);
                FMA2(accp[i][2], a2, bp2);
                FMA2(accp[i][3], a2, bp3);
            }
        }
        __syncthreads();
    }
    #pragma unroll
    for (int i = 0; i < 8; i++) {
        int r = rbase + (i < 4 ? ty * 4 + i : 64 + ty * 4 + (i - 4));
        if (r < NTN) {
            unsigned lo0, hi0, lo1, hi1;
            asm("mov.b64 {%0, %1}, %2;" : "=r"(lo0), "=r"(hi0) : "l"(accp[i][0]));
            asm("mov.b64 {%0, %1}, %2;" : "=r"(lo1), "=r"(hi1) : "l"(accp[i][1]));
            *reinterpret_cast<float4*>(&g_htail[(size_t)r * FOUT + tx * 4]) =
                make_float4(__uint_as_float(lo0), __uint_as_float(hi0),
                            __uint_as_float(lo1), __uint_as_float(hi1));
            asm("mov.b64 {%0, %1}, %2;" : "=r"(lo0), "=r"(hi0) : "l"(accp[i][2]));
            asm("mov.b64 {%0, %1}, %2;" : "=r"(lo1), "=r"(hi1) : "l"(accp[i][3]));
            *reinterpret_cast<float4*>(&g_htail[(size_t)r * FOUT + 64 + tx * 4]) =
                make_float4(__uint_as_float(lo0), __uint_as_float(hi0),
                            __uint_as_float(lo1), __uint_as_float(hi1));
        }
    }
}

__device__ __forceinline__ void edgeA_body(int bid, int tid,
                                           float* __restrict__ alpha_out,
                                           int write_alpha) {
    int e = bid * 256 + tid;
    if (e >= NE) return;
    int hi = g_hi[e];
    int ti = g_ti[e];
    int tt = (int)g_tt[e];
    float4 l = *reinterpret_cast<const float4*>(&g_hl[hi * NHEAD]);
    float4 r = *reinterpret_cast<const float4*>(&g_hr[ti * NHEAD]);
    float4 h = *reinterpret_cast<const float4*>(&g_he[tt * NHEAD]);
    float4 a;
    a.x = l.x + r.x + h.x; a.x = a.x >= 0.f ? a.x : NSLOPE * a.x;
    a.y = l.y + r.y + h.y; a.y = a.y >= 0.f ? a.y : NSLOPE * a.y;
    a.z = l.z + r.z + h.z; a.z = a.z >= 0.f ? a.z : NSLOPE * a.z;
    a.w = l.w + r.w + h.w; a.w = a.w >= 0.f ? a.w : NSLOPE * a.w;
    float4 ex;
    ex.x = expf(a.x); ex.y = expf(a.y); ex.z = expf(a.z); ex.w = expf(a.w);

    float* dp = &g_den[hi * NHEAD];
    asm volatile("red.global.add.v4.f32 [%0], {%1,%2,%3,%4};"
                 :: "l"(dp), "f"(ex.x), "f"(ex.y), "f"(ex.z), "f"(ex.w)
                 : "memory");

    if (write_alpha)    // unscaled ex, coalesced in e; rescaled in launch 5
        *reinterpret_cast<float4*>(&alpha_out[(size_t)e * NHEAD]) = ex;

    int pos = atomicAdd(&g_cur[hi], 1);
    g_sex[pos] = ex;
    g_sti[pos] = ti;
}

__global__ void __launch_bounds__(256, 2)
fat_kernel(const float* __restrict__ X, const float* __restrict__ W,
           float* __restrict__ alpha_out, int write_alpha) {
    __shared__ float As[8][128];
    __shared__ float Bs[8][128];
    int bid = blockIdx.x;
    int tid = threadIdx.x;
    if (bid < GEMM_PBLOCKS) {
        for (int tile = bid; tile < GEMM_TILES; tile += GEMM_PBLOCKS)
            gemm_tile(X, W, tile, tid, As, Bs);
    } else {
        edgeA_body(bid - GEMM_PBLOCKS, tid, alpha_out, write_alpha);
    }
}

// ========== launch 5: edgeC (1 warp/node, lane-staged indices) ∥ alpha rescale ==========
__device__ __forceinline__ float pick_h(const float4& v, int h) {
    return (h == 0) ? v.x : (h == 1) ? v.y : (h == 2) ? v.z : v.w;
}

__device__ __forceinline__ void edgeC_body(int bid, int tid,
                                           float* __restrict__ out) {
    int node = bid * 8 + (tid >> 5);
    int lane = tid & 31;
    int p0 = g_ptr[node], p1 = g_ptr[node + 1];
    int h = lane >> 3;

    float4 acc = make_float4(0.f, 0.f, 0.f, 0.f);

    // process edges in chunks of 32: one coalesced index load per chunk,
    // then shfl (off the memory path) feeds gather addresses — removes the
    // record-load -> gather dependency from the critical chain.
    for (int base = p0; base < p1; base += 32) {
        int cnt = p1 - base; if (cnt > 32) cnt = 32;
        int myt = (lane < cnt) ? g_sti[base + lane] : 0;
        int jj = 0;
        for (; jj + 4 <= cnt; jj += 4) {
            int t0 = __shfl_sync(0xffffffffu, myt, jj);
            int t1 = __shfl_sync(0xffffffffu, myt, jj + 1);
            int t2 = __shfl_sync(0xffffffffu, myt, jj + 2);
            int t3 = __shfl_sync(0xffffffffu, myt, jj + 3);
            float4 v0 = *reinterpret_cast<const float4*>(&g_htail[(size_t)t0 * FOUT + lane * 4]);
            float4 v1 = *reinterpret_cast<const float4*>(&g_htail[(size_t)t1 * FOUT + lane * 4]);
            float4 v2 = *reinterpret_cast<const float4*>(&g_htail[(size_t)t2 * FOUT + lane * 4]);
            float4 v3 = *reinterpret_cast<const float4*>(&g_htail[(size_t)t3 * FOUT + lane * 4]);
            float4 e0 = g_sex[base + jj];
            float4 e1 = g_sex[base + jj + 1];
            float4 e2 = g_sex[base + jj + 2];
            float4 e3 = g_sex[base + jj + 3];
            float a0 = pick_h(e0, h), a1 = pick_h(e1, h);
            float a2 = pick_h(e2, h), a3 = pick_h(e3, h);
            acc.x += a0 * v0.x; acc.y += a0 * v0.y; acc.z += a0 * v0.z; acc.w += a0 * v0.w;
            acc.x += a1 * v1.x; acc.y += a1 * v1.y; acc.z += a1 * v1.z; acc.w += a1 * v1.w;
            acc.x += a2 * v2.x; acc.y += a2 * v2.y; acc.z += a2 * v2.z; acc.w += a2 * v2.w;
            acc.x += a3 * v3.x; acc.y += a3 * v3.y; acc.z += a3 * v3.z; acc.w += a3 * v3.w;
        }
        for (; jj < cnt; jj++) {
            int t0 = __shfl_sync(0xffffffffu, myt, jj);
            float4 v0 = *reinterpret_cast<const float4*>(&g_htail[(size_t)t0 * FOUT + lane * 4]);
            float4 e0 = g_sex[base + jj];
            float a0 = pick_h(e0, h);
            acc.x += a0 * v0.x; acc.y += a0 * v0.y; acc.z += a0 * v0.z; acc.w += a0 * v0.w;
        }
    }

    float4 den = *reinterpret_cast<const float4*>(&g_den[node * NHEAD]);
    float d = pick_h(den, h);
    float rdh = d > 0.f ? 1.f / d : 0.f;
    acc.x *= rdh; acc.y *= rdh; acc.z *= rdh; acc.w *= rdh;
    acc.x = acc.x > 0.f ? acc.x : expm1f(acc.x);
    acc.y = acc.y > 0.f ? acc.y : expm1f(acc.y);
    acc.z = acc.z > 0.f ? acc.z : expm1f(acc.z);
    acc.w = acc.w > 0.f ? acc.w : expm1f(acc.w);
    *reinterpret_cast<float4*>(&out[(size_t)node * FOUT + lane * 4]) = acc;
}

__device__ __forceinline__ void rescale_body(int bid, int tid,
                                             float* __restrict__ alpha_out) {
    int e = bid * 256 + tid;
    if (e >= NE) return;
    int hi = g_hi[e];
    float4 den = *reinterpret_cast<const float4*>(&g_den[hi * NHEAD]);
    float4 rd;
    rd.x = den.x > 0.f ? 1.f / den.x : 0.f;
    rd.y = den.y > 0.f ? 1.f / den.y : 0.f;
    rd.z = den.z > 0.f ? 1.f / den.z : 0.f;
    rd.w = den.w > 0.f ? 1.f / den.w : 0.f;
    float4 al = *reinterpret_cast<const float4*>(&alpha_out[(size_t)e * NHEAD]);
    al.x *= rd.x; al.y *= rd.y; al.z *= rd.z; al.w *= rd.w;
    *reinterpret_cast<float4*>(&alpha_out[(size_t)e * NHEAD]) = al;
}

__global__ void edgeC_kernel(float* __restrict__ out,
                             float* __restrict__ alpha_out) {
    int bid = blockIdx.x;
    if (bid < NODE_BLOCKS) edgeC_body(bid, threadIdx.x, out);
    else rescale_body(bid - NODE_BLOCKS, threadIdx.x, alpha_out);
}

extern "C" void kernel_launch(void* const* d_in, const int* in_sizes, int n_in,
                              void* d_out, int out_size) {
    const float* headf = (const float*)d_in[0];
    const float* tailf = (const float*)d_in[1];
    const float* W     = (const float*)d_in[2];
    const float* We    = (const float*)d_in[3];
    const float* emb   = (const float*)d_in[4];
    const float* a_l   = (const float*)d_in[5];
    const float* a_r   = (const float*)d_in[6];
    const float* a_e   = (const float*)d_in[7];
    const void*  el    = d_in[8];
    const void*  te    = d_in[9];

    float* out   = (float*)d_out;
    float* alpha = out + (size_t)NHN * FOUT;
    int write_alpha = (out_size >= NHN * FOUT + NE * NHEAD) ? 1 : 0;

    init_kernel<<<256, 256>>>((const unsigned*)el, W, We, emb, a_l, a_r, a_e); // 1
    hist_kernel<<<(NE + 255) / 256, 256>>>(el, te);                            // 2
    scanlogits_kernel<<<1 + 3125, 256>>>(headf, tailf);                        // 3
    fat_kernel<<<GEMM_PBLOCKS + EDGEA_BLOCKS, 256>>>(tailf, W, alpha, write_alpha); // 4 <- profiled
    edgeC_kernel<<<NODE_BLOCKS + (write_alpha ? RES_BLOCKS : 0), 256>>>(out, alpha); // 5
}

// round 16
// speedup vs baseline: 1.1073x; 1.0499x over previous
#include <cuda_runtime.h>
#include <math.h>

#define NHN 50000          // head nodes
#define NTN 50000          // tail nodes
#define NE  1600000        // edges
#define INF 256            // in features
#define OUTF 32
#define NHEAD 4
#define EDGEF 64
#define NET 5
#define FOUT 128           // NHEAD*OUTF
#define NSLOPE 0.2f

#define GEMM_TILES  ((NTN + 127) / 128)            // 391
#define GEMM_PBLOCKS 196                           // persistent GEMM blocks
#define FOLD_BLOCKS 128                            // fold/zero blocks in hist launch
#define HIST_BLOCKS ((NE + 255) / 256)             // 6250
#define EDGEA_BLOCKS ((NE + 255) / 256)            // 6250
#define NODE_BLOCKS (NHN / 8)                      // 6250 (8 warps/block, 1 node/warp)
#define RES_BLOCKS  ((NE + 255) / 256)             // 6250

// packed f32x2 FMA: acc = a2 * b2 + acc  (per-half)
#define FMA2(acc, a2, b2) \
    asm("fma.rn.f32x2 %0, %1, %2, %0;" : "+l"(acc) : "l"(a2), "l"(b2))

// ---------------- static scratch (zero-initialized at load; maintained across runs) ----------------
__device__ __align__(16) float  g_htail[(size_t)NTN * FOUT];   // 25.6MB
__device__ __align__(16) float  g_hl[NHN * NHEAD];
__device__ __align__(16) float  g_hr[NTN * NHEAD];
__device__ __align__(16) float  g_he[NET * NHEAD];
__device__ __align__(16) float  g_Wl[NHEAD * INF];
__device__ __align__(16) float  g_Wr[NHEAD * INF];
__device__ __align__(16) float  g_den[NHN * NHEAD];
__device__ int    g_cnt[NHN];          // zeroed by previous run's edgeC (or static init)
__device__ int    g_ptr[NHN + 1];
__device__ int    g_cur[NHN];
__device__ __align__(16) float4 g_sex[NE];                     // 25.6MB sorted ex
__device__ int    g_sti[NE];                                   // 6.4MB  sorted tail idx
__device__ int    g_hi[NE];
__device__ int    g_ti[NE];
__device__ unsigned char g_tt[NE];

// ========== launch 1: fold blocks ∥ hist blocks (detect inline per warp) ==========
__device__ __forceinline__ void fold_body(int bid, int tid,
                                          const float* __restrict__ W,
                                          const float* __restrict__ We,
                                          const float* __restrict__ emb,
                                          const float* __restrict__ a_l,
                                          const float* __restrict__ a_r,
                                          const float* __restrict__ a_e) {
    int gtid = bid * 256 + tid;
    int stride = FOLD_BLOCKS * 256;
    for (int j = gtid; j < NHN * NHEAD; j += stride) g_den[j] = 0.f;
    if (gtid < NHEAD * INF) {
        int h = gtid >> 8;
        int k = gtid & 255;
        float sl = 0.f, sr = 0.f;
        #pragma unroll
        for (int d = 0; d < OUTF; d++) {
            float w = W[k * FOUT + h * OUTF + d];
            sl += w * a_l[h * OUTF + d];
            sr += w * a_r[h * OUTF + d];
        }
        g_Wl[gtid] = sl;
        g_Wr[gtid] = sr;
    }
    int gw = gtid >> 5, lane = gtid & 31;
    if (gw >= 32 && gw < 32 + NET * NHEAD) {
        int p = gw - 32;
        int t = p / NHEAD, h = p % NHEAD;
        float s = 0.f;
        #pragma unroll
        for (int half = 0; half < 2; half++) {
            int f = lane + half * 32;
            float ef = 0.f;
            #pragma unroll 8
            for (int k = 0; k < EDGEF; k++)
                ef += emb[t * EDGEF + k] * We[k * (NHEAD * EDGEF) + h * EDGEF + f];
            s += a_e[h * EDGEF + f] * ef;
        }
        #pragma unroll
        for (int off = 16; off; off >>= 1)
            s += __shfl_xor_sync(0xffffffffu, s, off);
        if (lane == 0) g_he[t * NHEAD + h] = s;
    }
}

__device__ __forceinline__ void hist_body(int bid, int tid,
                                          const unsigned* __restrict__ el_raw,
                                          const unsigned* __restrict__ te_raw) {
    int e = bid * 256 + tid;
    if (e >= NE) return;
    int lane = tid & 31;
    // per-warp dtype detection: odd 32-bit words of first 64 entries all-zero => int64
    unsigned w1 = el_raw[2 * lane + 1];
    unsigned w2 = el_raw[2 * lane + 65];
    int is64 = (__ballot_sync(0xffffffffu, (w1 | w2) != 0u) == 0u);

    int hi, ti, tt;
    if (is64) {
        hi = (int)((const long long*)el_raw)[e];
        ti = (int)((const long long*)el_raw)[NE + e];
        tt = (int)((const long long*)te_raw)[e];
    } else {
        hi = ((const int*)el_raw)[e];
        ti = ((const int*)el_raw)[NE + e];
        tt = ((const int*)te_raw)[e];
    }
    if (hi < 0) hi = 0; if (hi >= NHN) hi = NHN - 1;
    if (ti < 0) ti = 0; if (ti >= NTN) ti = NTN - 1;
    if (tt < 0) tt = 0; if (tt >= NET) tt = NET - 1;
    g_hi[e] = hi;
    g_ti[e] = ti;
    g_tt[e] = (unsigned char)tt;
    atomicAdd(&g_cnt[hi], 1);
}

__global__ void histfold_kernel(const unsigned* __restrict__ el_raw,
                                const unsigned* __restrict__ te_raw,
                                const float* __restrict__ W,
                                const float* __restrict__ We,
                                const float* __restrict__ emb,
                                const float* __restrict__ a_l,
                                const float* __restrict__ a_r,
                                const float* __restrict__ a_e) {
    int bid = blockIdx.x;
    if (bid < FOLD_BLOCKS) fold_body(bid, threadIdx.x, W, We, emb, a_l, a_r, a_e);
    else hist_body(bid - FOLD_BLOCKS, threadIdx.x, el_raw, te_raw);
}

// ========== launch 2: block 0 = exclusive scan, blocks 1+ = logits ==========
__device__ __forceinline__ void scan_body(int t) {
    __shared__ int s[256];
    const int C = (NHN + 255) / 256;   // 196
    int start = t * C; if (start > NHN) start = NHN;
    int end = start + C; if (end > NHN) end = NHN;
    int sum = 0;
    for (int i = start; i < end; i++) sum += g_cnt[i];
    s[t] = sum;
    __syncthreads();
    for (int off = 1; off < 256; off <<= 1) {
        int v = (t >= off) ? s[t - off] : 0;
        __syncthreads();
        s[t] += v;
        __syncthreads();
    }
    int run = s[t] - sum;
    for (int i = start; i < end; i++) {
        int c = g_cnt[i];
        g_ptr[i] = run;
        g_cur[i] = run;
        run += c;
    }
    if (t == 255) g_ptr[NHN] = run;
}

__device__ __forceinline__ void logits_body(const float* __restrict__ headf,
                                            const float* __restrict__ tailf,
                                            int bid, int tid) {
    const int GH = NHN / 4, GT = NTN / 4;
    int gw   = bid * 8 + (tid >> 5);
    int lane = tid & 31;
    if (gw >= GH + GT) return;
    const float* src; const float* Wp; float* dst; int r0;
    if (gw < GH) { r0 = gw * 4;        src = headf; Wp = g_Wl; dst = g_hl; }
    else         { r0 = (gw - GH) * 4; src = tailf; Wp = g_Wr; dst = g_hr; }

    float4 x0[4], x1[4];
    #pragma unroll
    for (int rr = 0; rr < 4; rr++) {
        const float4* x = reinterpret_cast<const float4*>(src + (size_t)(r0 + rr) * INF);
        x0[rr] = x[lane]; x1[rr] = x[lane + 32];
    }
    float4 w0[NHEAD], w1[NHEAD];
    #pragma unroll
    for (int h = 0; h < NHEAD; h++) {
        const float4* w = reinterpret_cast<const float4*>(Wp + h * INF);
        w0[h] = w[lane]; w1[h] = w[lane + 32];
    }
    #pragma unroll
    for (int rr = 0; rr < 4; rr++) {
        float p[NHEAD];
        #pragma unroll
        for (int h = 0; h < NHEAD; h++)
            p[h] = x0[rr].x*w0[h].x + x0[rr].y*w0[h].y + x0[rr].z*w0[h].z + x0[rr].w*w0[h].w
                 + x1[rr].x*w1[h].x + x1[rr].y*w1[h].y + x1[rr].z*w1[h].z + x1[rr].w*w1[h].w;
        #pragma unroll
        for (int off = 16; off; off >>= 1) {
            #pragma unroll
            for (int h = 0; h < NHEAD; h++)
                p[h] += __shfl_xor_sync(0xffffffffu, p[h], off);
        }
        if (lane == 0)
            *reinterpret_cast<float4*>(&dst[(r0 + rr) * NHEAD]) =
                make_float4(p[0], p[1], p[2], p[3]);
    }
}

__global__ void scanlogits_kernel(const float* __restrict__ headf,
                                  const float* __restrict__ tailf) {
    if (blockIdx.x == 0) scan_body(threadIdx.x);
    else logits_body(headf, tailf, blockIdx.x - 1, threadIdx.x);
}

// ========== launch 3: persistent GEMM ∥ edgeA ==========
__device__ __forceinline__ void gemm_tile(const float* __restrict__ X,
                                          const float* __restrict__ W,
                                          int tile, int tid,
                                          float As[8][128], float Bs[8][128]) {
    int tx = tid & 15, ty = tid >> 4;
    int rbase = tile * 128;

    unsigned long long accp[8][4];
    #pragma unroll
    for (int i = 0; i < 8; i++)
        #pragma unroll
        for (int j = 0; j < 4; j++) accp[i][j] = 0ull;

    for (int k0 = 0; k0 < INF; k0 += 8) {
        {
            int arow = rbase + (tid >> 1);
            int ar = arow < NTN ? arow : NTN - 1;
            const float4 av = *reinterpret_cast<const float4*>(
                X + (size_t)ar * INF + k0 + (tid & 1) * 4);
            int kp = (tid & 1) * 4;
            int rr = tid >> 1;
            As[kp + 0][rr] = av.x;
            As[kp + 1][rr] = av.y;
            As[kp + 2][rr] = av.z;
            As[kp + 3][rr] = av.w;
        }
        {
            const float4 bv = *reinterpret_cast<const float4*>(
                W + (size_t)(k0 + (tid >> 5)) * FOUT + (tid & 31) * 4);
            *reinterpret_cast<float4*>(&Bs[tid >> 5][(tid & 31) * 4]) = bv;
        }
        __syncthreads();
        #pragma unroll
        for (int kk = 0; kk < 8; kk++) {
            float a[8];
            float4 t0 = *reinterpret_cast<const float4*>(&As[kk][ty * 4]);
            float4 t1 = *reinterpret_cast<const float4*>(&As[kk][64 + ty * 4]);
            a[0]=t0.x; a[1]=t0.y; a[2]=t0.z; a[3]=t0.w;
            a[4]=t1.x; a[5]=t1.y; a[6]=t1.z; a[7]=t1.w;
            ulonglong2 b01 = *reinterpret_cast<const ulonglong2*>(&Bs[kk][tx * 4]);
            ulonglong2 b23 = *reinterpret_cast<const ulonglong2*>(&Bs[kk][64 + tx * 4]);
            unsigned long long bp0 = b01.x, bp1 = b01.y, bp2 = b23.x, bp3 = b23.y;
            #pragma unroll
            for (int i = 0; i < 8; i++) {
                unsigned long long a2;
                unsigned au = __float_as_uint(a[i]);
                asm("mov.b64 %0, {%1, %1};" : "=l"(a2) : "r"(au));
                FMA2(accp[i][0], a2, bp0);
                FMA2(accp[i][1], a2, bp1);
                FMA2(accp[i][2], a2, bp2);
                FMA2(accp[i][3], a2, bp3);
            }
        }
        __syncthreads();
    }
    #pragma unroll
    for (int i = 0; i < 8; i++) {
        int r = rbase + (i < 4 ? ty * 4 + i : 64 + ty * 4 + (i - 4));
        if (r < NTN) {
            unsigned lo0, hi0, lo1, hi1;
            asm("mov.b64 {%0, %1}, %2;" : "=r"(lo0), "=r"(hi0) : "l"(accp[i][0]));
            asm("mov.b64 {%0, %1}, %2;" : "=r"(lo1), "=r"(hi1) : "l"(accp[i][1]));
            *reinterpret_cast<float4*>(&g_htail[(size_t)r * FOUT + tx * 4]) =
                make_float4(__uint_as_float(lo0), __uint_as_float(hi0),
                            __uint_as_float(lo1), __uint_as_float(hi1));
            asm("mov.b64 {%0, %1}, %2;" : "=r"(lo0), "=r"(hi0) : "l"(accp[i][2]));
            asm("mov.b64 {%0, %1}, %2;" : "=r"(lo1), "=r"(hi1) : "l"(accp[i][3]));
            *reinterpret_cast<float4*>(&g_htail[(size_t)r * FOUT + 64 + tx * 4]) =
                make_float4(__uint_as_float(lo0), __uint_as_float(hi0),
                            __uint_as_float(lo1), __uint_as_float(hi1));
        }
    }
}

__device__ __forceinline__ void edgeA_body(int bid, int tid,
                                           float* __restrict__ alpha_out,
                                           int write_alpha) {
    int e = bid * 256 + tid;
    if (e >= NE) return;
    int hi = g_hi[e];
    int ti = g_ti[e];
    int tt = (int)g_tt[e];
    float4 l = *reinterpret_cast<const float4*>(&g_hl[hi * NHEAD]);
    float4 r = *reinterpret_cast<const float4*>(&g_hr[ti * NHEAD]);
    float4 h = *reinterpret_cast<const float4*>(&g_he[tt * NHEAD]);
    float4 a;
    a.x = l.x + r.x + h.x; a.x = a.x >= 0.f ? a.x : NSLOPE * a.x;
    a.y = l.y + r.y + h.y; a.y = a.y >= 0.f ? a.y : NSLOPE * a.y;
    a.z = l.z + r.z + h.z; a.z = a.z >= 0.f ? a.z : NSLOPE * a.z;
    a.w = l.w + r.w + h.w; a.w = a.w >= 0.f ? a.w : NSLOPE * a.w;
    float4 ex;
    ex.x = expf(a.x); ex.y = expf(a.y); ex.z = expf(a.z); ex.w = expf(a.w);

    float* dp = &g_den[hi * NHEAD];
    asm volatile("red.global.add.v4.f32 [%0], {%1,%2,%3,%4};"
                 :: "l"(dp), "f"(ex.x), "f"(ex.y), "f"(ex.z), "f"(ex.w)
                 : "memory");

    if (write_alpha)    // unscaled ex, coalesced in e; rescaled in launch 4
        *reinterpret_cast<float4*>(&alpha_out[(size_t)e * NHEAD]) = ex;

    int pos = atomicAdd(&g_cur[hi], 1);
    g_sex[pos] = ex;
    g_sti[pos] = ti;
}

__global__ void __launch_bounds__(256, 2)
fat_kernel(const float* __restrict__ X, const float* __restrict__ W,
           float* __restrict__ alpha_out, int write_alpha) {
    __shared__ float As[8][128];
    __shared__ float Bs[8][128];
    int bid = blockIdx.x;
    int tid = threadIdx.x;
    if (bid < GEMM_PBLOCKS) {
        for (int tile = bid; tile < GEMM_TILES; tile += GEMM_PBLOCKS)
            gemm_tile(X, W, tile, tid, As, Bs);
    } else {
        edgeA_body(bid - GEMM_PBLOCKS, tid, alpha_out, write_alpha);
    }
}

// ========== launch 4 (PROFILED): edgeC (all-staged, zero uniform loads) ∥ rescale ==========
__device__ __forceinline__ float pick_h(const float4& v, int h) {
    return (h == 0) ? v.x : (h == 1) ? v.y : (h == 2) ? v.z : v.w;
}

__device__ __forceinline__ void edgeC_body(int bid, int tid,
                                           float* __restrict__ out) {
    int node = bid * 8 + (tid >> 5);
    int lane = tid & 31;
    int p0 = g_ptr[node], p1 = g_ptr[node + 1];
    int h = lane >> 3;

    // tail maintenance for next graph replay: zero g_cnt (read only in launch 1/2)
    {
        int z = bid * 256 + tid;
        if (z < NHN) g_cnt[z] = 0;
    }

    const float* sexf = reinterpret_cast<const float*>(g_sex);
    float4 acc = make_float4(0.f, 0.f, 0.f, 0.f);

    for (int base = p0; base < p1; base += 32) {
        int cnt = p1 - base; if (cnt > 32) cnt = 32;
        // stage 32 tail indices: one coalesced load
        int myt = (lane < cnt) ? g_sti[base + lane] : 0;
        for (int sub = 0; sub < cnt; sub += 8) {
            // stage 8 edges' ex (32 floats): one coalesced load; lane L holds
            // component L&3 of edge sub + (L>>2)
            long long fidx = (long long)(base + sub) * 4 + lane;
            float myex = (fidx < (long long)p1 * 4) ? sexf[fidx] : 0.f;
            int scnt = cnt - sub; if (scnt > 8) scnt = 8;
            #pragma unroll 4
            for (int jj = 0; jj < scnt; jj++) {
                int t0 = __shfl_sync(0xffffffffu, myt, sub + jj);
                float a0 = __shfl_sync(0xffffffffu, myex, jj * 4 + h);
                float4 v0 = *reinterpret_cast<const float4*>(
                    &g_htail[(size_t)t0 * FOUT + lane * 4]);
                acc.x += a0 * v0.x; acc.y += a0 * v0.y;
                acc.z += a0 * v0.z; acc.w += a0 * v0.w;
            }
        }
    }

    float4 den = *reinterpret_cast<const float4*>(&g_den[node * NHEAD]);
    float d = pick_h(den, h);
    float rdh = d > 0.f ? 1.f / d : 0.f;
    acc.x *= rdh; acc.y *= rdh; acc.z *= rdh; acc.w *= rdh;
    acc.x = acc.x > 0.f ? acc.x : expm1f(acc.x);
    acc.y = acc.y > 0.f ? acc.y : expm1f(acc.y);
    acc.z = acc.z > 0.f ? acc.z : expm1f(acc.z);
    acc.w = acc.w > 0.f ? acc.w : expm1f(acc.w);
    *reinterpret_cast<float4*>(&out[(size_t)node * FOUT + lane * 4]) = acc;
}

__device__ __forceinline__ void rescale_body(int bid, int tid,
                                             float* __restrict__ alpha_out) {
    int e = bid * 256 + tid;
    if (e >= NE) return;
    int hi = g_hi[e];
    float4 den = *reinterpret_cast<const float4*>(&g_den[hi * NHEAD]);
    float4 rd;
    rd.x = den.x > 0.f ? 1.f / den.x : 0.f;
    rd.y = den.y > 0.f ? 1.f / den.y : 0.f;
    rd.z = den.z > 0.f ? 1.f / den.z : 0.f;
    rd.w = den.w > 0.f ? 1.f / den.w : 0.f;
    float4 al = *reinterpret_cast<const float4*>(&alpha_out[(size_t)e * NHEAD]);
    al.x *= rd.x; al.y *= rd.y; al.z *= rd.z; al.w *= rd.w;
    *reinterpret_cast<float4*>(&alpha_out[(size_t)e * NHEAD]) = al;
}

__global__ void edgeC_kernel(float* __restrict__ out,
                             float* __restrict__ alpha_out) {
    int bid = blockIdx.x;
    if (bid < NODE_BLOCKS) edgeC_body(bid, threadIdx.x, out);
    else rescale_body(bid - NODE_BLOCKS, threadIdx.x, alpha_out);
}

extern "C" void kernel_launch(void* const* d_in, const int* in_sizes, int n_in,
                              void* d_out, int out_size) {
    const float* headf = (const float*)d_in[0];
    const float* tailf = (const float*)d_in[1];
    const float* W     = (const float*)d_in[2];
    const float* We    = (const float*)d_in[3];
    const float* emb   = (const float*)d_in[4];
    const float* a_l   = (const float*)d_in[5];
    const float* a_r   = (const float*)d_in[6];
    const float* a_e   = (const float*)d_in[7];
    const unsigned* el = (const unsigned*)d_in[8];
    const unsigned* te = (const unsigned*)d_in[9];

    float* out   = (float*)d_out;
    float* alpha = out + (size_t)NHN * FOUT;
    int write_alpha = (out_size >= NHN * FOUT + NE * NHEAD) ? 1 : 0;

    histfold_kernel<<<FOLD_BLOCKS + HIST_BLOCKS, 256>>>(el, te, W, We, emb,
                                                        a_l, a_r, a_e);        // 1
    scanlogits_kernel<<<1 + 3125, 256>>>(headf, tailf);                        // 2
    fat_kernel<<<GEMM_PBLOCKS + EDGEA_BLOCKS, 256>>>(tailf, W, alpha, write_alpha); // 3
    edgeC_kernel<<<NODE_BLOCKS + (write_alpha ? RES_BLOCKS : 0), 256>>>(out, alpha); // 4 <- profiled
}